// round 1
// baseline (speedup 1.0000x reference)
#include <cuda_runtime.h>
#include <cstdint>
#include <cstddef>

#define NMAX 100000
#define EMAX 600000
#define FMAX 200000
#define C    128

// ---------------- scratch (static device globals; no runtime alloc) ----------
__device__ float g_x[(size_t)NMAX * C];      // features @ Wlin + blin
__device__ float g_num[(size_t)NMAX * C];    // weighted sums
__device__ float g_den[NMAX];                // weight sums
__device__ float g_nacc[NMAX * 3];           // accumulated / normalized normals
__device__ float g_w[EMAX];                  // edge weights
__device__ float g_stats[256];               // colsum[128], colsum2[128]
__device__ float g_mu[C];
__device__ float g_rstd[C];

// ---------------- zero helpers ----------------------------------------------
__global__ void k_zero(float* __restrict__ p, size_t n) {
    size_t i = (size_t)blockIdx.x * blockDim.x + threadIdx.x;
    if (i < n) p[i] = 0.0f;
}

// ---------------- face normals (scatter) -------------------------------------
__global__ void k_face(const int* __restrict__ faces, const float* __restrict__ verts,
                       float* __restrict__ nacc, int F) {
    int f = blockIdx.x * blockDim.x + threadIdx.x;
    if (f >= F) return;
    int i0 = __ldg(faces + f);
    int i1 = __ldg(faces + F + f);
    int i2 = __ldg(faces + 2 * F + f);
    float v0x = __ldg(verts + 3 * i0), v0y = __ldg(verts + 3 * i0 + 1), v0z = __ldg(verts + 3 * i0 + 2);
    float v1x = __ldg(verts + 3 * i1), v1y = __ldg(verts + 3 * i1 + 1), v1z = __ldg(verts + 3 * i1 + 2);
    float v2x = __ldg(verts + 3 * i2), v2y = __ldg(verts + 3 * i2 + 1), v2z = __ldg(verts + 3 * i2 + 2);
    float ax = v1x - v0x, ay = v1y - v0y, az = v1z - v0z;
    float bx = v2x - v0x, by = v2y - v0y, bz = v2z - v0z;
    float nx = ay * bz - az * by;
    float ny = az * bx - ax * bz;
    float nz = ax * by - ay * bx;
    atomicAdd(&nacc[3 * i0 + 0], nx); atomicAdd(&nacc[3 * i0 + 1], ny); atomicAdd(&nacc[3 * i0 + 2], nz);
    atomicAdd(&nacc[3 * i1 + 0], nx); atomicAdd(&nacc[3 * i1 + 1], ny); atomicAdd(&nacc[3 * i1 + 2], nz);
    atomicAdd(&nacc[3 * i2 + 0], nx); atomicAdd(&nacc[3 * i2 + 1], ny); atomicAdd(&nacc[3 * i2 + 2], nz);
}

__global__ void k_nnorm(float* __restrict__ nacc, int n) {
    int i = blockIdx.x * blockDim.x + threadIdx.x;
    if (i >= n) return;
    float x = nacc[3 * i], y = nacc[3 * i + 1], z = nacc[3 * i + 2];
    float len = sqrtf(x * x + y * y + z * z);
    float inv = 1.0f / (len + 1e-8f);
    nacc[3 * i] = x * inv; nacc[3 * i + 1] = y * inv; nacc[3 * i + 2] = z * inv;
}

// ---------------- vertex GEMM: x = feat @ W + b  (fp32 FFMA) ------------------
// block = 256 threads = 8 warps; each warp: 8 rows x 128 cols; lane: 8x4 tile.
__global__ __launch_bounds__(256) void k_gemm(const float* __restrict__ feat,
                                              const float* __restrict__ W,
                                              const float* __restrict__ bias,
                                              float* __restrict__ xout, int n) {
    int warp = threadIdx.x >> 5;
    int lane = threadIdx.x & 31;
    int row0 = blockIdx.x * 64 + warp * 8;
    int c0 = lane * 4;

    float4 bv = __ldg((const float4*)(bias + c0));
    float4 acc[8];
#pragma unroll
    for (int r = 0; r < 8; r++) acc[r] = bv;

    int rclamp[8];
#pragma unroll
    for (int r = 0; r < 8; r++) {
        int rr = row0 + r;
        rclamp[r] = (rr < n) ? rr : (n - 1);
    }

#pragma unroll 2
    for (int k = 0; k < 128; k += 4) {
        float4 w0 = __ldg((const float4*)(W + (size_t)(k + 0) * C + c0));
        float4 w1 = __ldg((const float4*)(W + (size_t)(k + 1) * C + c0));
        float4 w2 = __ldg((const float4*)(W + (size_t)(k + 2) * C + c0));
        float4 w3 = __ldg((const float4*)(W + (size_t)(k + 3) * C + c0));
#pragma unroll
        for (int r = 0; r < 8; r++) {
            float4 a = __ldg((const float4*)(feat + (size_t)rclamp[r] * C + k));
            acc[r].x += a.x * w0.x; acc[r].y += a.x * w0.y; acc[r].z += a.x * w0.z; acc[r].w += a.x * w0.w;
            acc[r].x += a.y * w1.x; acc[r].y += a.y * w1.y; acc[r].z += a.y * w1.z; acc[r].w += a.y * w1.w;
            acc[r].x += a.z * w2.x; acc[r].y += a.z * w2.y; acc[r].z += a.z * w2.z; acc[r].w += a.z * w2.w;
            acc[r].x += a.w * w3.x; acc[r].y += a.w * w3.y; acc[r].z += a.w * w3.z; acc[r].w += a.w * w3.w;
        }
    }
#pragma unroll
    for (int r = 0; r < 8; r++) {
        int rr = row0 + r;
        if (rr < n) *(float4*)(xout + (size_t)rr * C + c0) = acc[r];
    }
}

// ---------------- per-edge weight: w = exp(-||S t||^2) ------------------------
__global__ __launch_bounds__(256) void k_edge_w(const int* __restrict__ edges,
                                                const float* __restrict__ verts,
                                                const float* __restrict__ normals,
                                                const float* __restrict__ W1,
                                                const float* __restrict__ b1,
                                                const float* __restrict__ W2,
                                                const float* __restrict__ b2,
                                                float* __restrict__ wout,
                                                float* __restrict__ den, int E) {
    __shared__ float sW1[96];   // [d*32 + j]
    __shared__ float sb1[32];
    __shared__ float sW2[192];  // [j*6 + m]
    __shared__ float sb2[6];
    int tid = threadIdx.x;
    for (int i = tid; i < 96;  i += blockDim.x) sW1[i] = W1[i];
    for (int i = tid; i < 32;  i += blockDim.x) sb1[i] = b1[i];
    for (int i = tid; i < 192; i += blockDim.x) sW2[i] = W2[i];
    for (int i = tid; i < 6;   i += blockDim.x) sb2[i] = b2[i];
    __syncthreads();

    int e = blockIdx.x * blockDim.x + tid;
    if (e >= E) return;
    int src = __ldg(edges + e);
    int dst = __ldg(edges + E + e);

    float dx = __ldg(verts + 3 * dst)     - __ldg(verts + 3 * src);
    float dy = __ldg(verts + 3 * dst + 1) - __ldg(verts + 3 * src + 1);
    float dz = __ldg(verts + 3 * dst + 2) - __ldg(verts + 3 * src + 2);
    float nx = normals[3 * src], ny = normals[3 * src + 1], nz = normals[3 * src + 2];
    float dot = dx * nx + dy * ny + dz * nz;
    float t0 = dx - dot * nx, t1 = dy - dot * ny, t2 = dz - dot * nz;

    float th[6];
#pragma unroll
    for (int m = 0; m < 6; m++) th[m] = sb2[m];
#pragma unroll
    for (int j = 0; j < 32; j++) {
        float h = sb1[j] + t0 * sW1[j] + t1 * sW1[32 + j] + t2 * sW1[64 + j];
        h = fmaxf(h, 0.0f);
#pragma unroll
        for (int m = 0; m < 6; m++) th[m] += h * sW2[j * 6 + m];
    }
    // q = || S t ||^2  (S symmetric, M = S*S)
    float s0 = th[0] * t0 + th[1] * t1 + th[2] * t2;
    float s1 = th[1] * t0 + th[3] * t1 + th[4] * t2;
    float s2 = th[2] * t0 + th[4] * t1 + th[5] * t2;
    float q = s0 * s0 + s1 * s1 + s2 * s2;
    float wv = expf(-q);
    wout[e] = wv;
    atomicAdd(&den[dst], wv);
}

// ---------------- aggregation: num[dst] += w * x[src] (warp per edge) --------
__global__ __launch_bounds__(256) void k_agg(const int* __restrict__ edges,
                                             const float* __restrict__ w,
                                             const float* __restrict__ x,
                                             float* __restrict__ num, int E) {
    int gw = (blockIdx.x * blockDim.x + threadIdx.x) >> 5;
    int lane = threadIdx.x & 31;
    if (gw >= E) return;
    int src = __ldg(edges + gw);
    int dst = __ldg(edges + E + gw);
    float we = __ldg(w + gw);
    float4 v = __ldg((const float4*)(x + (size_t)src * C) + lane);
    float4* np = (float4*)(num + (size_t)dst * C) + lane;
    asm volatile("red.global.add.v4.f32 [%0], {%1, %2, %3, %4};"
                 :: "l"(np), "f"(v.x * we), "f"(v.y * we), "f"(v.z * we), "f"(v.w * we)
                 : "memory");
}

// ---------------- per-column stats -------------------------------------------
__global__ void k_stats(const float* __restrict__ num, const float* __restrict__ den,
                        float* __restrict__ stats, int n) {
    int c = threadIdx.x;  // 128 threads
    float s1 = 0.0f, s2 = 0.0f;
    for (int r = blockIdx.x; r < n; r += gridDim.x) {
        float rd = 1.0f / (__ldg(den + r) + 1e-5f);
        float p = __ldg(num + (size_t)r * C + c) * rd;
        s1 += p;
        s2 += p * p;
    }
    atomicAdd(&stats[c], s1);
    atomicAdd(&stats[C + c], s2);
}

__global__ void k_finalize(const float* __restrict__ stats, float* __restrict__ mu,
                           float* __restrict__ rstd, int n) {
    int c = threadIdx.x;
    float m = stats[c] / (float)n;
    float var = (stats[C + c] - (float)n * m * m) / (float)(n - 1);
    var = fmaxf(var, 0.0f);
    mu[c] = m;
    rstd[c] = 1.0f / (sqrtf(var) + 1e-5f);
}

// ---------------- final: normalize + ELU -------------------------------------
__global__ void k_final(const float* __restrict__ num, const float* __restrict__ den,
                        const float* __restrict__ mu, const float* __restrict__ rstd,
                        float* __restrict__ out, int n) {
    size_t idx = (size_t)blockIdx.x * blockDim.x + threadIdx.x;
    if (idx >= (size_t)n * C) return;
    int r = (int)(idx >> 7);
    int c = (int)(idx & 127);
    float p = num[idx] / (__ldg(den + r) + 1e-5f);
    float y = (p - __ldg(mu + c)) * __ldg(rstd + c);
    out[idx] = (y > 0.0f) ? y : expm1f(y);
}

// ---------------- launch -----------------------------------------------------
extern "C" void kernel_launch(void* const* d_in, const int* in_sizes, int n_in,
                              void* d_out, int out_size) {
    const float* features = (const float*)d_in[0];
    const float* vertices = (const float*)d_in[1];
    const int*   edges    = (const int*)d_in[2];
    const int*   faces    = (const int*)d_in[3];
    const float* W1       = (const float*)d_in[4];
    const float* b1       = (const float*)d_in[5];
    const float* W2       = (const float*)d_in[6];
    const float* b2       = (const float*)d_in[7];
    const float* Wlin     = (const float*)d_in[8];
    const float* blin     = (const float*)d_in[9];

    int n = in_sizes[0] / C;
    int e = in_sizes[2] / 2;
    int f = in_sizes[3] / 3;
    if (n > NMAX) n = NMAX;
    if (e > EMAX) e = EMAX;
    if (f > FMAX) f = FMAX;

    float *p_x, *p_num, *p_den, *p_nacc, *p_w, *p_stats, *p_mu, *p_rstd;
    cudaGetSymbolAddress((void**)&p_x, g_x);
    cudaGetSymbolAddress((void**)&p_num, g_num);
    cudaGetSymbolAddress((void**)&p_den, g_den);
    cudaGetSymbolAddress((void**)&p_nacc, g_nacc);
    cudaGetSymbolAddress((void**)&p_w, g_w);
    cudaGetSymbolAddress((void**)&p_stats, g_stats);
    cudaGetSymbolAddress((void**)&p_mu, g_mu);
    cudaGetSymbolAddress((void**)&p_rstd, g_rstd);

    float* out = (float*)d_out;

    // zero accumulators
    k_zero<<<(n * 3 + 255) / 256, 256>>>(p_nacc, (size_t)n * 3);
    k_zero<<<((size_t)n * C + 255) / 256, 256>>>(p_num, (size_t)n * C);
    k_zero<<<(n + 255) / 256, 256>>>(p_den, (size_t)n);
    k_zero<<<1, 256>>>(p_stats, 256);

    // geometry
    k_face<<<(f + 255) / 256, 256>>>(faces, vertices, p_nacc, f);
    k_nnorm<<<(n + 255) / 256, 256>>>(p_nacc, n);

    // vertex linear transform
    k_gemm<<<(n + 63) / 64, 256>>>(features, Wlin, blin, p_x, n);

    // edge weights + denominator
    k_edge_w<<<(e + 255) / 256, 256>>>(edges, vertices, p_nacc, W1, b1, W2, b2,
                                       p_w, p_den, e);

    // weighted aggregation (warp per edge)
    k_agg<<<(e + 7) / 8, 256>>>(edges, p_w, p_x, p_num, e);

    // column stats -> normalize + ELU
    k_stats<<<512, 128>>>(p_num, p_den, p_stats, n);
    k_finalize<<<1, C>>>(p_stats, p_mu, p_rstd, n);
    k_final<<<((size_t)n * C + 255) / 256, 256>>>(p_num, p_den, p_mu, p_rstd, out, n);
}

// round 6
// speedup vs baseline: 1.2000x; 1.2000x over previous
#include <cuda_runtime.h>
#include <cuda_bf16.h>
#include <cstdint>
#include <cstddef>

#define NMAX 100000
#define EMAX 600000
#define FMAX 200000
#define C    128

// ---------------- scratch (static device globals; no runtime alloc) ----------
__device__ float g_x[(size_t)NMAX * C];      // features @ Wlin + blin
__device__ float g_num[(size_t)NMAX * C];    // weighted sums
__device__ float g_den[NMAX];                // weight sums
__device__ float g_nacc[NMAX * 3];           // accumulated / normalized normals
__device__ float g_w[EMAX];                  // edge weights
__device__ float g_stats[256];               // colsum[128], colsum2[128]
__device__ float g_mu[C];
__device__ float g_rstd[C];
// pre-converted W as bf16 hi/lo pairs, layout [n][k-pair] with pitch 68 u32
#define BPITCH 68
__device__ uint32_t g_Bh[128 * BPITCH];
__device__ uint32_t g_Bl[128 * BPITCH];

// ---------------- zero helpers ----------------------------------------------
__global__ void k_zero(float* __restrict__ p, size_t n) {
    size_t i = (size_t)blockIdx.x * blockDim.x + threadIdx.x;
    if (i < n) p[i] = 0.0f;
}

__global__ void k_zero_misc(float* __restrict__ nacc, float* __restrict__ den,
                            float* __restrict__ stats, int n) {
    int i = blockIdx.x * blockDim.x + threadIdx.x;
    if (i < n * 3) nacc[i] = 0.0f;
    if (i < n) den[i] = 0.0f;
    if (i < 256) stats[i] = 0.0f;
}

// ---------------- face normals (scatter) -------------------------------------
__global__ void k_face(const int* __restrict__ faces, const float* __restrict__ verts,
                       float* __restrict__ nacc, int F) {
    int f = blockIdx.x * blockDim.x + threadIdx.x;
    if (f >= F) return;
    int i0 = __ldg(faces + f);
    int i1 = __ldg(faces + F + f);
    int i2 = __ldg(faces + 2 * F + f);
    float v0x = __ldg(verts + 3 * i0), v0y = __ldg(verts + 3 * i0 + 1), v0z = __ldg(verts + 3 * i0 + 2);
    float v1x = __ldg(verts + 3 * i1), v1y = __ldg(verts + 3 * i1 + 1), v1z = __ldg(verts + 3 * i1 + 2);
    float v2x = __ldg(verts + 3 * i2), v2y = __ldg(verts + 3 * i2 + 1), v2z = __ldg(verts + 3 * i2 + 2);
    float ax = v1x - v0x, ay = v1y - v0y, az = v1z - v0z;
    float bx = v2x - v0x, by = v2y - v0y, bz = v2z - v0z;
    float nx = ay * bz - az * by;
    float ny = az * bx - ax * bz;
    float nz = ax * by - ay * bx;
    atomicAdd(&nacc[3 * i0 + 0], nx); atomicAdd(&nacc[3 * i0 + 1], ny); atomicAdd(&nacc[3 * i0 + 2], nz);
    atomicAdd(&nacc[3 * i1 + 0], nx); atomicAdd(&nacc[3 * i1 + 1], ny); atomicAdd(&nacc[3 * i1 + 2], nz);
    atomicAdd(&nacc[3 * i2 + 0], nx); atomicAdd(&nacc[3 * i2 + 1], ny); atomicAdd(&nacc[3 * i2 + 2], nz);
}

__global__ void k_nnorm(float* __restrict__ nacc, int n) {
    int i = blockIdx.x * blockDim.x + threadIdx.x;
    if (i >= n) return;
    float x = nacc[3 * i], y = nacc[3 * i + 1], z = nacc[3 * i + 2];
    float len = sqrtf(x * x + y * y + z * z);
    float inv = 1.0f / (len + 1e-8f);
    nacc[3 * i] = x * inv; nacc[3 * i + 1] = y * inv; nacc[3 * i + 2] = z * inv;
}

// ---------------- W pre-convert: fp32 -> bf16 hi/lo [n][k] pitch-68 ----------
__global__ void k_prepB(const float* __restrict__ W, uint32_t* __restrict__ bh,
                        uint32_t* __restrict__ bl) {
    int idx = blockIdx.x * blockDim.x + threadIdx.x;   // 128 cols * 64 k-pairs
    if (idx >= 128 * 64) return;
    int c = idx >> 6, kp = idx & 63;
    float v0 = __ldg(W + (size_t)(2 * kp) * C + c);
    float v1 = __ldg(W + (size_t)(2 * kp + 1) * C + c);
    __nv_bfloat16 h0 = __float2bfloat16_rn(v0);
    __nv_bfloat16 h1 = __float2bfloat16_rn(v1);
    __nv_bfloat16 l0 = __float2bfloat16_rn(v0 - __bfloat162float(h0));
    __nv_bfloat16 l1 = __float2bfloat16_rn(v1 - __bfloat162float(h1));
    __nv_bfloat162 H(h0, h1), L(l0, l1);
    bh[c * BPITCH + kp] = *(uint32_t*)&H;
    bl[c * BPITCH + kp] = *(uint32_t*)&L;
}

// ---------------- mma.sync helpers -------------------------------------------
__device__ __forceinline__ void mma16816(float* c, const uint32_t* a,
                                         uint32_t b0, uint32_t b1) {
    asm volatile(
        "mma.sync.aligned.m16n8k16.row.col.f32.bf16.bf16.f32 "
        "{%0,%1,%2,%3}, {%4,%5,%6,%7}, {%8,%9}, {%0,%1,%2,%3};"
        : "+f"(c[0]), "+f"(c[1]), "+f"(c[2]), "+f"(c[3])
        : "r"(a[0]), "r"(a[1]), "r"(a[2]), "r"(a[3]), "r"(b0), "r"(b1));
}

__device__ __forceinline__ void cvt2(float2 v, uint32_t& hi, uint32_t& lo) {
    __nv_bfloat16 h0 = __float2bfloat16_rn(v.x);
    __nv_bfloat16 h1 = __float2bfloat16_rn(v.y);
    __nv_bfloat16 l0 = __float2bfloat16_rn(v.x - __bfloat162float(h0));
    __nv_bfloat16 l1 = __float2bfloat16_rn(v.y - __bfloat162float(h1));
    __nv_bfloat162 H(h0, h1), L(l0, l1);
    hi = *(uint32_t*)&H;
    lo = *(uint32_t*)&L;
}

// ---------------- bf16x3 mma GEMM: x = feat @ W + b --------------------------
// 256 threads = 8 warps; CTA tile 128x128; warp: 16 rows x 128 cols.
extern __shared__ uint32_t sB[];   // [2][128*BPITCH] hi then lo

__global__ __launch_bounds__(256) void k_gemm_mma(const float* __restrict__ feat,
                                                  const uint32_t* __restrict__ gBh,
                                                  const uint32_t* __restrict__ gBl,
                                                  const float* __restrict__ bias,
                                                  float* __restrict__ xout, int n) {
    const int BSZ = 128 * BPITCH;          // 8704 u32
    int tid = threadIdx.x;
    // copy pre-converted B into smem (float4, 2176 vec4 per matrix)
    {
        const float4* s1 = (const float4*)gBh;
        const float4* s2 = (const float4*)gBl;
        float4* d1 = (float4*)sB;
        float4* d2 = (float4*)(sB + BSZ);
        for (int i = tid; i < BSZ / 4; i += 256) { d1[i] = __ldg(s1 + i); d2[i] = __ldg(s2 + i); }
    }
    __syncthreads();

    int warp = tid >> 5, lane = tid & 31;
    int gid = lane >> 2, tg = lane & 3;
    int r0 = blockIdx.x * 128 + warp * 16 + gid;
    int r1 = r0 + 8;
    int r0c = (r0 < n) ? r0 : (n - 1);
    int r1c = (r1 < n) ? r1 : (n - 1);
    const float* A0 = feat + (size_t)r0c * C;
    const float* A1 = feat + (size_t)r1c * C;

    float acc[16][4];
#pragma unroll
    for (int t = 0; t < 16; t++) { acc[t][0] = acc[t][1] = acc[t][2] = acc[t][3] = 0.0f; }

    const uint32_t* Bh = sB;
    const uint32_t* Bl = sB + BSZ;

#pragma unroll
    for (int ch = 0; ch < 8; ch++) {
        int k0 = ch * 16 + tg * 2;
        float2 p00 = __ldg((const float2*)(A0 + k0));
        float2 p10 = __ldg((const float2*)(A1 + k0));
        float2 p01 = __ldg((const float2*)(A0 + k0 + 8));
        float2 p11 = __ldg((const float2*)(A1 + k0 + 8));
        uint32_t ah[4], al[4];
        cvt2(p00, ah[0], al[0]);
        cvt2(p10, ah[1], al[1]);
        cvt2(p01, ah[2], al[2]);
        cvt2(p11, ah[3], al[3]);
        int bbase = ch * 8 + tg;
#pragma unroll
        for (int t = 0; t < 16; t++) {
            int ci = (t * 8 + gid) * BPITCH + bbase;
            uint32_t bh0 = Bh[ci], bh1 = Bh[ci + 4];
            uint32_t bl0 = Bl[ci], bl1 = Bl[ci + 4];
            mma16816(acc[t], ah, bh0, bh1);
            mma16816(acc[t], ah, bl0, bl1);
            mma16816(acc[t], al, bh0, bh1);
        }
    }

    // epilogue: +bias, direct float2 stores (lanes 0-3 cover 32B contiguous)
#pragma unroll
    for (int t = 0; t < 16; t++) {
        int c0 = t * 8 + tg * 2;
        float2 bv = __ldg((const float2*)(bias + c0));
        if (r0 < n) {
            float2 o = make_float2(acc[t][0] + bv.x, acc[t][1] + bv.y);
            *(float2*)(xout + (size_t)r0 * C + c0) = o;
        }
        if (r1 < n) {
            float2 o = make_float2(acc[t][2] + bv.x, acc[t][3] + bv.y);
            *(float2*)(xout + (size_t)r1 * C + c0) = o;
        }
    }
}

// ---------------- per-edge weight: w = exp(-||S t||^2) ------------------------
__global__ __launch_bounds__(256) void k_edge_w(const int* __restrict__ edges,
                                                const float* __restrict__ verts,
                                                const float* __restrict__ normals,
                                                const float* __restrict__ W1,
                                                const float* __restrict__ b1,
                                                const float* __restrict__ W2,
                                                const float* __restrict__ b2,
                                                float* __restrict__ wout,
                                                float* __restrict__ den, int E) {
    __shared__ float sW1[96];
    __shared__ float sb1[32];
    __shared__ float sW2[192];
    __shared__ float sb2[6];
    int tid = threadIdx.x;
    for (int i = tid; i < 96;  i += blockDim.x) sW1[i] = W1[i];
    for (int i = tid; i < 32;  i += blockDim.x) sb1[i] = b1[i];
    for (int i = tid; i < 192; i += blockDim.x) sW2[i] = W2[i];
    for (int i = tid; i < 6;   i += blockDim.x) sb2[i] = b2[i];
    __syncthreads();

    int e = blockIdx.x * blockDim.x + tid;
    if (e >= E) return;
    int src = __ldg(edges + e);
    int dst = __ldg(edges + E + e);

    float dx = __ldg(verts + 3 * dst)     - __ldg(verts + 3 * src);
    float dy = __ldg(verts + 3 * dst + 1) - __ldg(verts + 3 * src + 1);
    float dz = __ldg(verts + 3 * dst + 2) - __ldg(verts + 3 * src + 2);
    float nx = normals[3 * src], ny = normals[3 * src + 1], nz = normals[3 * src + 2];
    float dot = dx * nx + dy * ny + dz * nz;
    float t0 = dx - dot * nx, t1 = dy - dot * ny, t2 = dz - dot * nz;

    float th[6];
#pragma unroll
    for (int m = 0; m < 6; m++) th[m] = sb2[m];
#pragma unroll
    for (int j = 0; j < 32; j++) {
        float h = sb1[j] + t0 * sW1[j] + t1 * sW1[32 + j] + t2 * sW1[64 + j];
        h = fmaxf(h, 0.0f);
#pragma unroll
        for (int m = 0; m < 6; m++) th[m] += h * sW2[j * 6 + m];
    }
    float s0 = th[0] * t0 + th[1] * t1 + th[2] * t2;
    float s1 = th[1] * t0 + th[3] * t1 + th[4] * t2;
    float s2 = th[2] * t0 + th[4] * t1 + th[5] * t2;
    float q = s0 * s0 + s1 * s1 + s2 * s2;
    float wv = expf(-q);
    wout[e] = wv;
    atomicAdd(&den[dst], wv);
}

// ---------------- aggregation: num[dst] += w * x[src] (warp per edge) --------
__global__ __launch_bounds__(256) void k_agg(const int* __restrict__ edges,
                                             const float* __restrict__ w,
                                             const float* __restrict__ x,
                                             float* __restrict__ num, int E) {
    int gw = (blockIdx.x * blockDim.x + threadIdx.x) >> 5;
    int lane = threadIdx.x & 31;
    if (gw >= E) return;
    int src = __ldg(edges + gw);
    int dst = __ldg(edges + E + gw);
    float we = __ldg(w + gw);
    float4 v = __ldg((const float4*)(x + (size_t)src * C) + lane);
    float4* np = (float4*)(num + (size_t)dst * C) + lane;
    asm volatile("red.global.add.v4.f32 [%0], {%1, %2, %3, %4};"
                 :: "l"(np), "f"(v.x * we), "f"(v.y * we), "f"(v.z * we), "f"(v.w * we)
                 : "memory");
}

// ---------------- per-column stats -------------------------------------------
__global__ void k_stats(const float* __restrict__ num, const float* __restrict__ den,
                        float* __restrict__ stats, int n) {
    int c = threadIdx.x;  // 128 threads
    float s1 = 0.0f, s2 = 0.0f;
    for (int r = blockIdx.x; r < n; r += gridDim.x) {
        float rd = 1.0f / (__ldg(den + r) + 1e-5f);
        float p = __ldg(num + (size_t)r * C + c) * rd;
        s1 += p;
        s2 += p * p;
    }
    atomicAdd(&stats[c], s1);
    atomicAdd(&stats[C + c], s2);
}

__global__ void k_finalize(const float* __restrict__ stats, float* __restrict__ mu,
                           float* __restrict__ rstd, int n) {
    int c = threadIdx.x;
    float m = stats[c] / (float)n;
    float var = (stats[C + c] - (float)n * m * m) / (float)(n - 1);
    var = fmaxf(var, 0.0f);
    mu[c] = m;
    rstd[c] = 1.0f / (sqrtf(var) + 1e-5f);
}

// ---------------- final: normalize + ELU -------------------------------------
__global__ void k_final(const float* __restrict__ num, const float* __restrict__ den,
                        const float* __restrict__ mu, const float* __restrict__ rstd,
                        float* __restrict__ out, int n) {
    size_t idx = (size_t)blockIdx.x * blockDim.x + threadIdx.x;
    if (idx >= (size_t)n * C) return;
    int r = (int)(idx >> 7);
    int c = (int)(idx & 127);
    float p = num[idx] / (__ldg(den + r) + 1e-5f);
    float y = (p - __ldg(mu + c)) * __ldg(rstd + c);
    out[idx] = (y > 0.0f) ? y : expm1f(y);
}

// ---------------- launch -----------------------------------------------------
extern "C" void kernel_launch(void* const* d_in, const int* in_sizes, int n_in,
                              void* d_out, int out_size) {
    const float* features = (const float*)d_in[0];
    const float* vertices = (const float*)d_in[1];
    const int*   edges    = (const int*)d_in[2];
    const int*   faces    = (const int*)d_in[3];
    const float* W1       = (const float*)d_in[4];
    const float* b1       = (const float*)d_in[5];
    const float* W2       = (const float*)d_in[6];
    const float* b2       = (const float*)d_in[7];
    const float* Wlin     = (const float*)d_in[8];
    const float* blin     = (const float*)d_in[9];

    int n = in_sizes[0] / C;
    int e = in_sizes[2] / 2;
    int f = in_sizes[3] / 3;
    if (n > NMAX) n = NMAX;
    if (e > EMAX) e = EMAX;
    if (f > FMAX) f = FMAX;

    float *p_x, *p_num, *p_den, *p_nacc, *p_w, *p_stats, *p_mu, *p_rstd;
    uint32_t *p_bh, *p_bl;
    cudaGetSymbolAddress((void**)&p_x, g_x);
    cudaGetSymbolAddress((void**)&p_num, g_num);
    cudaGetSymbolAddress((void**)&p_den, g_den);
    cudaGetSymbolAddress((void**)&p_nacc, g_nacc);
    cudaGetSymbolAddress((void**)&p_w, g_w);
    cudaGetSymbolAddress((void**)&p_stats, g_stats);
    cudaGetSymbolAddress((void**)&p_mu, g_mu);
    cudaGetSymbolAddress((void**)&p_rstd, g_rstd);
    cudaGetSymbolAddress((void**)&p_bh, g_Bh);
    cudaGetSymbolAddress((void**)&p_bl, g_Bl);

    float* out = (float*)d_out;

    const int GEMM_SMEM = 2 * 128 * BPITCH * 4;   // 69632 bytes
    cudaFuncSetAttribute(k_gemm_mma, cudaFuncAttributeMaxDynamicSharedMemorySize, GEMM_SMEM);

    // launch index 5 = k_gemm_mma (ncu -s 5 -c 1 profiles it)
    k_zero<<<((size_t)n * C + 255) / 256, 256>>>(p_num, (size_t)n * C);            // 0
    k_zero_misc<<<(n * 3 + 255) / 256, 256>>>(p_nacc, p_den, p_stats, n);          // 1
    k_face<<<(f + 255) / 256, 256>>>(faces, vertices, p_nacc, f);                  // 2
    k_nnorm<<<(n + 255) / 256, 256>>>(p_nacc, n);                                  // 3
    k_prepB<<<32, 256>>>(Wlin, p_bh, p_bl);                                        // 4
    k_gemm_mma<<<(n + 127) / 128, 256, GEMM_SMEM>>>(features, p_bh, p_bl,
                                                    blin, p_x, n);                 // 5
    k_edge_w<<<(e + 255) / 256, 256>>>(edges, vertices, p_nacc, W1, b1, W2, b2,
                                       p_w, p_den, e);                             // 6
    k_agg<<<(e + 7) / 8, 256>>>(edges, p_w, p_x, p_num, e);                        // 7
    k_stats<<<512, 128>>>(p_num, p_den, p_stats, n);                               // 8
    k_finalize<<<1, C>>>(p_stats, p_mu, p_rstd, n);                                // 9
    k_final<<<((size_t)n * C + 255) / 256, 256>>>(p_num, p_den, p_mu, p_rstd, out, n); // 10
}

// round 7
// speedup vs baseline: 1.6740x; 1.3951x over previous
#include <cuda_runtime.h>
#include <cuda_bf16.h>
#include <cstdint>
#include <cstddef>

#define NMAX 100000
#define EMAX 600000
#define FMAX 200000
#define C    128

// ---------------- scratch (static device globals; no runtime alloc) ----------
__device__ float g_x[(size_t)NMAX * C];      // features @ Wlin + blin
__device__ float g_p[(size_t)NMAX * C];      // aggregated & den-normalized rows
__device__ float g_nacc[NMAX * 3];           // accumulated / normalized normals
__device__ float g_w[EMAX];                  // edge weights
__device__ float g_stats[256];               // colsum[128], colsum2[128]
__device__ float g_mu[C];
__device__ float g_rstd[C];
// CSR-by-dst
__device__ int   g_deg[NMAX];
__device__ int   g_scan[NMAX];               // in-block exclusive scan
__device__ int   g_part[128];                // block partial sums
__device__ int   g_partscan[128];
__device__ int   g_start[NMAX + 1];
__device__ int   g_cursor[NMAX];
__device__ int   g_csr_src[EMAX];
__device__ float g_csr_w[EMAX];
// pre-converted W as bf16 hi/lo pairs, layout [n][k-pair] with pitch 68 u32
#define BPITCH 68
__device__ uint32_t g_Bh[128 * BPITCH];
__device__ uint32_t g_Bl[128 * BPITCH];

// ---------------- zero helper ------------------------------------------------
__global__ void k_zero_misc(float* __restrict__ nacc, int* __restrict__ deg,
                            float* __restrict__ stats, int n) {
    int i = blockIdx.x * blockDim.x + threadIdx.x;
    if (i < n * 3) nacc[i] = 0.0f;
    if (i < n) deg[i] = 0;
    if (i < 256) stats[i] = 0.0f;
}

// ---------------- face normals (scatter) -------------------------------------
__global__ void k_face(const int* __restrict__ faces, const float* __restrict__ verts,
                       float* __restrict__ nacc, int F) {
    int f = blockIdx.x * blockDim.x + threadIdx.x;
    if (f >= F) return;
    int i0 = __ldg(faces + f);
    int i1 = __ldg(faces + F + f);
    int i2 = __ldg(faces + 2 * F + f);
    float v0x = __ldg(verts + 3 * i0), v0y = __ldg(verts + 3 * i0 + 1), v0z = __ldg(verts + 3 * i0 + 2);
    float v1x = __ldg(verts + 3 * i1), v1y = __ldg(verts + 3 * i1 + 1), v1z = __ldg(verts + 3 * i1 + 2);
    float v2x = __ldg(verts + 3 * i2), v2y = __ldg(verts + 3 * i2 + 1), v2z = __ldg(verts + 3 * i2 + 2);
    float ax = v1x - v0x, ay = v1y - v0y, az = v1z - v0z;
    float bx = v2x - v0x, by = v2y - v0y, bz = v2z - v0z;
    float nx = ay * bz - az * by;
    float ny = az * bx - ax * bz;
    float nz = ax * by - ay * bx;
    atomicAdd(&nacc[3 * i0 + 0], nx); atomicAdd(&nacc[3 * i0 + 1], ny); atomicAdd(&nacc[3 * i0 + 2], nz);
    atomicAdd(&nacc[3 * i1 + 0], nx); atomicAdd(&nacc[3 * i1 + 1], ny); atomicAdd(&nacc[3 * i1 + 2], nz);
    atomicAdd(&nacc[3 * i2 + 0], nx); atomicAdd(&nacc[3 * i2 + 1], ny); atomicAdd(&nacc[3 * i2 + 2], nz);
}

__global__ void k_nnorm(float* __restrict__ nacc, int n) {
    int i = blockIdx.x * blockDim.x + threadIdx.x;
    if (i >= n) return;
    float x = nacc[3 * i], y = nacc[3 * i + 1], z = nacc[3 * i + 2];
    float len = sqrtf(x * x + y * y + z * z);
    float inv = 1.0f / (len + 1e-8f);
    nacc[3 * i] = x * inv; nacc[3 * i + 1] = y * inv; nacc[3 * i + 2] = z * inv;
}

// ---------------- W pre-convert: fp32 -> bf16 hi/lo [n][k] pitch-68 ----------
__global__ void k_prepB(const float* __restrict__ W, uint32_t* __restrict__ bh,
                        uint32_t* __restrict__ bl) {
    int idx = blockIdx.x * blockDim.x + threadIdx.x;   // 128 cols * 64 k-pairs
    if (idx >= 128 * 64) return;
    int c = idx >> 6, kp = idx & 63;
    float v0 = __ldg(W + (size_t)(2 * kp) * C + c);
    float v1 = __ldg(W + (size_t)(2 * kp + 1) * C + c);
    __nv_bfloat16 h0 = __float2bfloat16_rn(v0);
    __nv_bfloat16 h1 = __float2bfloat16_rn(v1);
    __nv_bfloat16 l0 = __float2bfloat16_rn(v0 - __bfloat162float(h0));
    __nv_bfloat16 l1 = __float2bfloat16_rn(v1 - __bfloat162float(h1));
    __nv_bfloat162 H(h0, h1), L(l0, l1);
    bh[c * BPITCH + kp] = *(uint32_t*)&H;
    bl[c * BPITCH + kp] = *(uint32_t*)&L;
}

// ---------------- mma.sync helpers -------------------------------------------
__device__ __forceinline__ void mma16816(float* c, const uint32_t* a,
                                         uint32_t b0, uint32_t b1) {
    asm volatile(
        "mma.sync.aligned.m16n8k16.row.col.f32.bf16.bf16.f32 "
        "{%0,%1,%2,%3}, {%4,%5,%6,%7}, {%8,%9}, {%0,%1,%2,%3};"
        : "+f"(c[0]), "+f"(c[1]), "+f"(c[2]), "+f"(c[3])
        : "r"(a[0]), "r"(a[1]), "r"(a[2]), "r"(a[3]), "r"(b0), "r"(b1));
}

__device__ __forceinline__ void cvt2(float2 v, uint32_t& hi, uint32_t& lo) {
    __nv_bfloat16 h0 = __float2bfloat16_rn(v.x);
    __nv_bfloat16 h1 = __float2bfloat16_rn(v.y);
    __nv_bfloat16 l0 = __float2bfloat16_rn(v.x - __bfloat162float(h0));
    __nv_bfloat16 l1 = __float2bfloat16_rn(v.y - __bfloat162float(h1));
    __nv_bfloat162 H(h0, h1), L(l0, l1);
    hi = *(uint32_t*)&H;
    lo = *(uint32_t*)&L;
}

// ---------------- bf16x3 mma GEMM: x = feat @ W + b --------------------------
extern __shared__ uint32_t sB[];   // [2][128*BPITCH] hi then lo

__global__ __launch_bounds__(256) void k_gemm_mma(const float* __restrict__ feat,
                                                  const uint32_t* __restrict__ gBh,
                                                  const uint32_t* __restrict__ gBl,
                                                  const float* __restrict__ bias,
                                                  float* __restrict__ xout, int n) {
    const int BSZ = 128 * BPITCH;          // 8704 u32
    int tid = threadIdx.x;
    {
        const float4* s1 = (const float4*)gBh;
        const float4* s2 = (const float4*)gBl;
        float4* d1 = (float4*)sB;
        float4* d2 = (float4*)(sB + BSZ);
        for (int i = tid; i < BSZ / 4; i += 256) { d1[i] = __ldg(s1 + i); d2[i] = __ldg(s2 + i); }
    }
    __syncthreads();

    int warp = tid >> 5, lane = tid & 31;
    int gid = lane >> 2, tg = lane & 3;
    int r0 = blockIdx.x * 128 + warp * 16 + gid;
    int r1 = r0 + 8;
    int r0c = (r0 < n) ? r0 : (n - 1);
    int r1c = (r1 < n) ? r1 : (n - 1);
    const float* A0 = feat + (size_t)r0c * C;
    const float* A1 = feat + (size_t)r1c * C;

    float acc[16][4];
#pragma unroll
    for (int t = 0; t < 16; t++) { acc[t][0] = acc[t][1] = acc[t][2] = acc[t][3] = 0.0f; }

    const uint32_t* Bh = sB;
    const uint32_t* Bl = sB + BSZ;

#pragma unroll
    for (int ch = 0; ch < 8; ch++) {
        int k0 = ch * 16 + tg * 2;
        float2 p00 = __ldg((const float2*)(A0 + k0));
        float2 p10 = __ldg((const float2*)(A1 + k0));
        float2 p01 = __ldg((const float2*)(A0 + k0 + 8));
        float2 p11 = __ldg((const float2*)(A1 + k0 + 8));
        uint32_t ah[4], al[4];
        cvt2(p00, ah[0], al[0]);
        cvt2(p10, ah[1], al[1]);
        cvt2(p01, ah[2], al[2]);
        cvt2(p11, ah[3], al[3]);
        int bbase = ch * 8 + tg;
#pragma unroll
        for (int t = 0; t < 16; t++) {
            int ci = (t * 8 + gid) * BPITCH + bbase;
            uint32_t bh0 = Bh[ci], bh1 = Bh[ci + 4];
            uint32_t bl0 = Bl[ci], bl1 = Bl[ci + 4];
            mma16816(acc[t], ah, bh0, bh1);
            mma16816(acc[t], ah, bl0, bl1);
            mma16816(acc[t], al, bh0, bh1);
        }
    }

#pragma unroll
    for (int t = 0; t < 16; t++) {
        int c0 = t * 8 + tg * 2;
        float2 bv = __ldg((const float2*)(bias + c0));
        if (r0 < n) {
            float2 o = make_float2(acc[t][0] + bv.x, acc[t][1] + bv.y);
            *(float2*)(xout + (size_t)r0 * C + c0) = o;
        }
        if (r1 < n) {
            float2 o = make_float2(acc[t][2] + bv.x, acc[t][3] + bv.y);
            *(float2*)(xout + (size_t)r1 * C + c0) = o;
        }
    }
}

// ---------------- per-edge weight + dst degree count -------------------------
__global__ __launch_bounds__(256) void k_edge_w(const int* __restrict__ edges,
                                                const float* __restrict__ verts,
                                                const float* __restrict__ normals,
                                                const float* __restrict__ W1,
                                                const float* __restrict__ b1,
                                                const float* __restrict__ W2,
                                                const float* __restrict__ b2,
                                                float* __restrict__ wout,
                                                int* __restrict__ deg, int E) {
    __shared__ float sW1[96];
    __shared__ float sb1[32];
    __shared__ float sW2[192];
    __shared__ float sb2[6];
    int tid = threadIdx.x;
    for (int i = tid; i < 96;  i += blockDim.x) sW1[i] = W1[i];
    for (int i = tid; i < 32;  i += blockDim.x) sb1[i] = b1[i];
    for (int i = tid; i < 192; i += blockDim.x) sW2[i] = W2[i];
    for (int i = tid; i < 6;   i += blockDim.x) sb2[i] = b2[i];
    __syncthreads();

    int e = blockIdx.x * blockDim.x + tid;
    if (e >= E) return;
    int src = __ldg(edges + e);
    int dst = __ldg(edges + E + e);

    float dx = __ldg(verts + 3 * dst)     - __ldg(verts + 3 * src);
    float dy = __ldg(verts + 3 * dst + 1) - __ldg(verts + 3 * src + 1);
    float dz = __ldg(verts + 3 * dst + 2) - __ldg(verts + 3 * src + 2);
    float nx = normals[3 * src], ny = normals[3 * src + 1], nz = normals[3 * src + 2];
    float dot = dx * nx + dy * ny + dz * nz;
    float t0 = dx - dot * nx, t1 = dy - dot * ny, t2 = dz - dot * nz;

    float th[6];
#pragma unroll
    for (int m = 0; m < 6; m++) th[m] = sb2[m];
#pragma unroll
    for (int j = 0; j < 32; j++) {
        float h = sb1[j] + t0 * sW1[j] + t1 * sW1[32 + j] + t2 * sW1[64 + j];
        h = fmaxf(h, 0.0f);
#pragma unroll
        for (int m = 0; m < 6; m++) th[m] += h * sW2[j * 6 + m];
    }
    float s0 = th[0] * t0 + th[1] * t1 + th[2] * t2;
    float s1 = th[1] * t0 + th[3] * t1 + th[4] * t2;
    float s2 = th[2] * t0 + th[4] * t1 + th[5] * t2;
    float q = s0 * s0 + s1 * s1 + s2 * s2;
    wout[e] = expf(-q);
    atomicAdd(&deg[dst], 1);
}

// ---------------- two-level exclusive scan over deg --------------------------
// block: 256 threads x 4 elems = 1024 elems
__global__ __launch_bounds__(256) void k_scan_block(const int* __restrict__ deg,
                                                    int* __restrict__ scan,
                                                    int* __restrict__ part, int n) {
    __shared__ int sd[256];
    int t = threadIdx.x;
    int base = blockIdx.x * 1024 + t * 4;
    int d0 = (base + 0 < n) ? deg[base + 0] : 0;
    int d1 = (base + 1 < n) ? deg[base + 1] : 0;
    int d2 = (base + 2 < n) ? deg[base + 2] : 0;
    int d3 = (base + 3 < n) ? deg[base + 3] : 0;
    int s = d0 + d1 + d2 + d3;
    sd[t] = s;
#pragma unroll
    for (int off = 1; off < 256; off <<= 1) {
        __syncthreads();
        int v = (t >= off) ? sd[t - off] : 0;
        __syncthreads();
        sd[t] += v;
    }
    __syncthreads();
    int excl = sd[t] - s;
    if (base + 0 < n) scan[base + 0] = excl;
    if (base + 1 < n) scan[base + 1] = excl + d0;
    if (base + 2 < n) scan[base + 2] = excl + d0 + d1;
    if (base + 3 < n) scan[base + 3] = excl + d0 + d1 + d2;
    if (t == 255) part[blockIdx.x] = sd[255];
}

__global__ void k_scan_part(const int* __restrict__ part, int* __restrict__ partscan,
                            int nb) {
    __shared__ int sd[128];
    int t = threadIdx.x;
    int s = (t < nb) ? part[t] : 0;
    sd[t] = s;
#pragma unroll
    for (int off = 1; off < 128; off <<= 1) {
        __syncthreads();
        int v = (t >= off) ? sd[t - off] : 0;
        __syncthreads();
        sd[t] += v;
    }
    __syncthreads();
    if (t < nb) partscan[t] = sd[t] - s;
}

__global__ void k_scan_add(const int* __restrict__ scan, const int* __restrict__ partscan,
                           int* __restrict__ start, int* __restrict__ cursor,
                           int n, int E) {
    int i = blockIdx.x * blockDim.x + threadIdx.x;
    if (i < n) {
        int v = scan[i] + partscan[i >> 10];
        start[i] = v;
        cursor[i] = v;
    }
    if (i == 0) start[n] = E;
}

// ---------------- CSR fill ----------------------------------------------------
__global__ void k_fill(const int* __restrict__ edges, const float* __restrict__ w,
                       int* __restrict__ cursor, int* __restrict__ csr_src,
                       float* __restrict__ csr_w, int E) {
    int e = blockIdx.x * blockDim.x + threadIdx.x;
    if (e >= E) return;
    int src = __ldg(edges + e);
    int dst = __ldg(edges + E + e);
    int pos = atomicAdd(&cursor[dst], 1);
    csr_src[pos] = src;
    csr_w[pos] = w[e];
}

// ---------------- gather aggregation: warp per dst vertex --------------------
__global__ __launch_bounds__(256) void k_gather(const int* __restrict__ start,
                                                const int* __restrict__ csr_src,
                                                const float* __restrict__ csr_w,
                                                const float* __restrict__ x,
                                                float* __restrict__ p, int n) {
    int v = (blockIdx.x * blockDim.x + threadIdx.x) >> 5;
    int lane = threadIdx.x & 31;
    if (v >= n) return;
    int beg = __ldg(start + v);
    int end = __ldg(start + v + 1);
    float4 acc = make_float4(0.f, 0.f, 0.f, 0.f);
    float dsum = 0.0f;
    for (int i = beg; i < end; i++) {
        int s = __ldg(csr_src + i);
        float we = __ldg(csr_w + i);
        float4 xv = __ldg((const float4*)(x + (size_t)s * C) + lane);
        dsum += we;
        acc.x += we * xv.x; acc.y += we * xv.y; acc.z += we * xv.z; acc.w += we * xv.w;
    }
    float rd = 1.0f / (dsum + 1e-5f);
    acc.x *= rd; acc.y *= rd; acc.z *= rd; acc.w *= rd;
    *((float4*)(p + (size_t)v * C) + lane) = acc;
}

// ---------------- per-column stats -------------------------------------------
__global__ void k_stats(const float* __restrict__ p, float* __restrict__ stats, int n) {
    int c = threadIdx.x;  // 128 threads
    float s1 = 0.0f, s2 = 0.0f;
    for (int r = blockIdx.x; r < n; r += gridDim.x) {
        float v = __ldg(p + (size_t)r * C + c);
        s1 += v;
        s2 += v * v;
    }
    atomicAdd(&stats[c], s1);
    atomicAdd(&stats[C + c], s2);
}

__global__ void k_finalize(const float* __restrict__ stats, float* __restrict__ mu,
                           float* __restrict__ rstd, int n) {
    int c = threadIdx.x;
    float m = stats[c] / (float)n;
    float var = (stats[C + c] - (float)n * m * m) / (float)(n - 1);
    var = fmaxf(var, 0.0f);
    mu[c] = m;
    rstd[c] = 1.0f / (sqrtf(var) + 1e-5f);
}

// ---------------- final: normalize + ELU -------------------------------------
__global__ void k_final(const float* __restrict__ p, const float* __restrict__ mu,
                        const float* __restrict__ rstd, float* __restrict__ out, int n) {
    size_t idx = (size_t)blockIdx.x * blockDim.x + threadIdx.x;
    if (idx >= (size_t)n * C) return;
    int c = (int)(idx & 127);
    float y = (p[idx] - __ldg(mu + c)) * __ldg(rstd + c);
    out[idx] = (y > 0.0f) ? y : expm1f(y);
}

// ---------------- launch -----------------------------------------------------
extern "C" void kernel_launch(void* const* d_in, const int* in_sizes, int n_in,
                              void* d_out, int out_size) {
    const float* features = (const float*)d_in[0];
    const float* vertices = (const float*)d_in[1];
    const int*   edges    = (const int*)d_in[2];
    const int*   faces    = (const int*)d_in[3];
    const float* W1       = (const float*)d_in[4];
    const float* b1       = (const float*)d_in[5];
    const float* W2       = (const float*)d_in[6];
    const float* b2       = (const float*)d_in[7];
    const float* Wlin     = (const float*)d_in[8];
    const float* blin     = (const float*)d_in[9];

    int n = in_sizes[0] / C;
    int e = in_sizes[2] / 2;
    int f = in_sizes[3] / 3;
    if (n > NMAX) n = NMAX;
    if (e > EMAX) e = EMAX;
    if (f > FMAX) f = FMAX;

    float *p_x, *p_p, *p_nacc, *p_w, *p_stats, *p_mu, *p_rstd, *p_csrw;
    int *p_deg, *p_scan, *p_part, *p_partscan, *p_start, *p_cursor, *p_csrsrc;
    uint32_t *p_bh, *p_bl;
    cudaGetSymbolAddress((void**)&p_x, g_x);
    cudaGetSymbolAddress((void**)&p_p, g_p);
    cudaGetSymbolAddress((void**)&p_nacc, g_nacc);
    cudaGetSymbolAddress((void**)&p_w, g_w);
    cudaGetSymbolAddress((void**)&p_stats, g_stats);
    cudaGetSymbolAddress((void**)&p_mu, g_mu);
    cudaGetSymbolAddress((void**)&p_rstd, g_rstd);
    cudaGetSymbolAddress((void**)&p_deg, g_deg);
    cudaGetSymbolAddress((void**)&p_scan, g_scan);
    cudaGetSymbolAddress((void**)&p_part, g_part);
    cudaGetSymbolAddress((void**)&p_partscan, g_partscan);
    cudaGetSymbolAddress((void**)&p_start, g_start);
    cudaGetSymbolAddress((void**)&p_cursor, g_cursor);
    cudaGetSymbolAddress((void**)&p_csrsrc, g_csr_src);
    cudaGetSymbolAddress((void**)&p_csrw, g_csr_w);
    cudaGetSymbolAddress((void**)&p_bh, g_Bh);
    cudaGetSymbolAddress((void**)&p_bl, g_Bl);

    float* out = (float*)d_out;

    const int GEMM_SMEM = 2 * 128 * BPITCH * 4;   // 69632 bytes
    cudaFuncSetAttribute(k_gemm_mma, cudaFuncAttributeMaxDynamicSharedMemorySize, GEMM_SMEM);

    int nb = (n + 1023) / 1024;                   // scan blocks (<=128)

    k_zero_misc<<<(n * 3 + 255) / 256, 256>>>(p_nacc, p_deg, p_stats, n);
    k_face<<<(f + 255) / 256, 256>>>(faces, vertices, p_nacc, f);
    k_nnorm<<<(n + 255) / 256, 256>>>(p_nacc, n);
    k_prepB<<<32, 256>>>(Wlin, p_bh, p_bl);
    k_gemm_mma<<<(n + 127) / 128, 256, GEMM_SMEM>>>(features, p_bh, p_bl,
                                                    blin, p_x, n);
    k_edge_w<<<(e + 255) / 256, 256>>>(edges, vertices, p_nacc, W1, b1, W2, b2,
                                       p_w, p_deg, e);
    k_scan_block<<<nb, 256>>>(p_deg, p_scan, p_part, n);
    k_scan_part<<<1, 128>>>(p_part, p_partscan, nb);
    k_scan_add<<<(n + 255) / 256, 256>>>(p_scan, p_partscan, p_start, p_cursor, n, e);
    k_fill<<<(e + 255) / 256, 256>>>(edges, p_w, p_cursor, p_csrsrc, p_csrw, e);
    k_gather<<<(n * 32 + 255) / 256, 256>>>(p_start, p_csrsrc, p_csrw, p_x, p_p, n);
    k_stats<<<512, 128>>>(p_p, p_stats, n);
    k_finalize<<<1, C>>>(p_stats, p_mu, p_rstd, n);
    k_final<<<((size_t)n * C + 255) / 256, 256>>>(p_p, p_mu, p_rstd, out, n);
}

// round 9
// speedup vs baseline: 1.6989x; 1.0149x over previous
#include <cuda_runtime.h>
#include <cuda_bf16.h>
#include <cstdint>
#include <cstddef>

#define NMAX 100000
#define EMAX 600000
#define FMAX 200000
#define C    128

// ---------------- scratch (static device globals; no runtime alloc) ----------
__device__ float g_x[(size_t)NMAX * C];      // features @ Wlin + blin
__device__ float g_p[(size_t)NMAX * C];      // aggregated & den-normalized rows
__device__ float g_nacc[NMAX * 3];           // accumulated face normals (raw)
__device__ float g_stats[256];               // colsum[128], colsum2[128]
__device__ float g_mu[C];
__device__ float g_rstd[C];
// CSR-by-dst
__device__ int   g_deg[NMAX];
__device__ int   g_scan[NMAX];               // in-block exclusive scan
__device__ int   g_part[128];                // block partial sums
__device__ int   g_partscan[128];
__device__ int   g_start[NMAX + 1];
__device__ int   g_cursor[NMAX];
__device__ int   g_csr_src[EMAX];
__device__ float g_csr_w[EMAX];
// pre-converted W as bf16 hi/lo pairs, layout [n][k-pair] with pitch 68 u32
#define BPITCH 68
__device__ uint32_t g_Bh[128 * BPITCH];
__device__ uint32_t g_Bl[128 * BPITCH];

// ---------------- zero helper ------------------------------------------------
__global__ void k_zero_misc(float* __restrict__ nacc, int* __restrict__ deg,
                            float* __restrict__ stats, int n) {
    int i = blockIdx.x * blockDim.x + threadIdx.x;
    if (i < n * 3) nacc[i] = 0.0f;
    if (i < n) deg[i] = 0;
    if (i < 256) stats[i] = 0.0f;
}

// ---------------- dst degree count -------------------------------------------
__global__ void k_count(const int* __restrict__ edges, int* __restrict__ deg, int E) {
    int e = blockIdx.x * blockDim.x + threadIdx.x;
    if (e < E) atomicAdd(&deg[__ldg(edges + E + e)], 1);
}

// ---------------- face normals (scatter) -------------------------------------
__global__ void k_face(const int* __restrict__ faces, const float* __restrict__ verts,
                       float* __restrict__ nacc, int F) {
    int f = blockIdx.x * blockDim.x + threadIdx.x;
    if (f >= F) return;
    int i0 = __ldg(faces + f);
    int i1 = __ldg(faces + F + f);
    int i2 = __ldg(faces + 2 * F + f);
    float v0x = __ldg(verts + 3 * i0), v0y = __ldg(verts + 3 * i0 + 1), v0z = __ldg(verts + 3 * i0 + 2);
    float v1x = __ldg(verts + 3 * i1), v1y = __ldg(verts + 3 * i1 + 1), v1z = __ldg(verts + 3 * i1 + 2);
    float v2x = __ldg(verts + 3 * i2), v2y = __ldg(verts + 3 * i2 + 1), v2z = __ldg(verts + 3 * i2 + 2);
    float ax = v1x - v0x, ay = v1y - v0y, az = v1z - v0z;
    float bx = v2x - v0x, by = v2y - v0y, bz = v2z - v0z;
    float nx = ay * bz - az * by;
    float ny = az * bx - ax * bz;
    float nz = ax * by - ay * bx;
    atomicAdd(&nacc[3 * i0 + 0], nx); atomicAdd(&nacc[3 * i0 + 1], ny); atomicAdd(&nacc[3 * i0 + 2], nz);
    atomicAdd(&nacc[3 * i1 + 0], nx); atomicAdd(&nacc[3 * i1 + 1], ny); atomicAdd(&nacc[3 * i1 + 2], nz);
    atomicAdd(&nacc[3 * i2 + 0], nx); atomicAdd(&nacc[3 * i2 + 1], ny); atomicAdd(&nacc[3 * i2 + 2], nz);
}

// ---------------- W pre-convert: fp32 -> bf16 hi/lo [n][k] pitch-68 ----------
__global__ void k_prepB(const float* __restrict__ W, uint32_t* __restrict__ bh,
                        uint32_t* __restrict__ bl) {
    int idx = blockIdx.x * blockDim.x + threadIdx.x;   // 128 cols * 64 k-pairs
    if (idx >= 128 * 64) return;
    int c = idx >> 6, kp = idx & 63;
    float v0 = __ldg(W + (size_t)(2 * kp) * C + c);
    float v1 = __ldg(W + (size_t)(2 * kp + 1) * C + c);
    __nv_bfloat16 h0 = __float2bfloat16_rn(v0);
    __nv_bfloat16 h1 = __float2bfloat16_rn(v1);
    __nv_bfloat16 l0 = __float2bfloat16_rn(v0 - __bfloat162float(h0));
    __nv_bfloat16 l1 = __float2bfloat16_rn(v1 - __bfloat162float(h1));
    __nv_bfloat162 H(h0, h1), L(l0, l1);
    bh[c * BPITCH + kp] = *(uint32_t*)&H;
    bl[c * BPITCH + kp] = *(uint32_t*)&L;
}

// ---------------- mma.sync helpers -------------------------------------------
__device__ __forceinline__ void mma16816(float* c, const uint32_t* a,
                                         uint32_t b0, uint32_t b1) {
    asm volatile(
        "mma.sync.aligned.m16n8k16.row.col.f32.bf16.bf16.f32 "
        "{%0,%1,%2,%3}, {%4,%5,%6,%7}, {%8,%9}, {%0,%1,%2,%3};"
        : "+f"(c[0]), "+f"(c[1]), "+f"(c[2]), "+f"(c[3])
        : "r"(a[0]), "r"(a[1]), "r"(a[2]), "r"(a[3]), "r"(b0), "r"(b1));
}

__device__ __forceinline__ void cvt2(float2 v, uint32_t& hi, uint32_t& lo) {
    __nv_bfloat16 h0 = __float2bfloat16_rn(v.x);
    __nv_bfloat16 h1 = __float2bfloat16_rn(v.y);
    __nv_bfloat16 l0 = __float2bfloat16_rn(v.x - __bfloat162float(h0));
    __nv_bfloat16 l1 = __float2bfloat16_rn(v.y - __bfloat162float(h1));
    __nv_bfloat162 H(h0, h1), L(l0, l1);
    hi = *(uint32_t*)&H;
    lo = *(uint32_t*)&L;
}

// ---------------- bf16x3 mma GEMM: x = feat @ W + b --------------------------
extern __shared__ uint32_t sB[];   // [2][128*BPITCH] hi then lo

__global__ __launch_bounds__(256) void k_gemm_mma(const float* __restrict__ feat,
                                                  const uint32_t* __restrict__ gBh,
                                                  const uint32_t* __restrict__ gBl,
                                                  const float* __restrict__ bias,
                                                  float* __restrict__ xout, int n) {
    const int BSZ = 128 * BPITCH;          // 8704 u32
    int tid = threadIdx.x;
    {
        const float4* s1 = (const float4*)gBh;
        const float4* s2 = (const float4*)gBl;
        float4* d1 = (float4*)sB;
        float4* d2 = (float4*)(sB + BSZ);
        for (int i = tid; i < BSZ / 4; i += 256) { d1[i] = __ldg(s1 + i); d2[i] = __ldg(s2 + i); }
    }
    __syncthreads();

    int warp = tid >> 5, lane = tid & 31;
    int gid = lane >> 2, tg = lane & 3;
    int r0 = blockIdx.x * 128 + warp * 16 + gid;
    int r1 = r0 + 8;
    int r0c = (r0 < n) ? r0 : (n - 1);
    int r1c = (r1 < n) ? r1 : (n - 1);
    const float* A0 = feat + (size_t)r0c * C;
    const float* A1 = feat + (size_t)r1c * C;

    float acc[16][4];
#pragma unroll
    for (int t = 0; t < 16; t++) { acc[t][0] = acc[t][1] = acc[t][2] = acc[t][3] = 0.0f; }

    const uint32_t* Bh = sB;
    const uint32_t* Bl = sB + BSZ;

#pragma unroll
    for (int ch = 0; ch < 8; ch++) {
        int k0 = ch * 16 + tg * 2;
        float2 p00 = __ldg((const float2*)(A0 + k0));
        float2 p10 = __ldg((const float2*)(A1 + k0));
        float2 p01 = __ldg((const float2*)(A0 + k0 + 8));
        float2 p11 = __ldg((const float2*)(A1 + k0 + 8));
        uint32_t ah[4], al[4];
        cvt2(p00, ah[0], al[0]);
        cvt2(p10, ah[1], al[1]);
        cvt2(p01, ah[2], al[2]);
        cvt2(p11, ah[3], al[3]);
        int bbase = ch * 8 + tg;
#pragma unroll
        for (int t = 0; t < 16; t++) {
            int ci = (t * 8 + gid) * BPITCH + bbase;
            uint32_t bh0 = Bh[ci], bh1 = Bh[ci + 4];
            uint32_t bl0 = Bl[ci], bl1 = Bl[ci + 4];
            mma16816(acc[t], ah, bh0, bh1);
            mma16816(acc[t], ah, bl0, bl1);
            mma16816(acc[t], al, bh0, bh1);
        }
    }

#pragma unroll
    for (int t = 0; t < 16; t++) {
        int c0 = t * 8 + tg * 2;
        float2 bv = __ldg((const float2*)(bias + c0));
        if (r0 < n) {
            float2 o = make_float2(acc[t][0] + bv.x, acc[t][1] + bv.y);
            *(float2*)(xout + (size_t)r0 * C + c0) = o;
        }
        if (r1 < n) {
            float2 o = make_float2(acc[t][2] + bv.x, acc[t][3] + bv.y);
            *(float2*)(xout + (size_t)r1 * C + c0) = o;
        }
    }
}

// ---------------- two-level exclusive scan over deg --------------------------
__global__ __launch_bounds__(256) void k_scan_block(const int* __restrict__ deg,
                                                    int* __restrict__ scan,
                                                    int* __restrict__ part, int n) {
    __shared__ int sd[256];
    int t = threadIdx.x;
    int base = blockIdx.x * 1024 + t * 4;
    int d0 = (base + 0 < n) ? deg[base + 0] : 0;
    int d1 = (base + 1 < n) ? deg[base + 1] : 0;
    int d2 = (base + 2 < n) ? deg[base + 2] : 0;
    int d3 = (base + 3 < n) ? deg[base + 3] : 0;
    int s = d0 + d1 + d2 + d3;
    sd[t] = s;
#pragma unroll
    for (int off = 1; off < 256; off <<= 1) {
        __syncthreads();
        int v = (t >= off) ? sd[t - off] : 0;
        __syncthreads();
        sd[t] += v;
    }
    __syncthreads();
    int excl = sd[t] - s;
    if (base + 0 < n) scan[base + 0] = excl;
    if (base + 1 < n) scan[base + 1] = excl + d0;
    if (base + 2 < n) scan[base + 2] = excl + d0 + d1;
    if (base + 3 < n) scan[base + 3] = excl + d0 + d1 + d2;
    if (t == 255) part[blockIdx.x] = sd[255];
}

__global__ void k_scan_part(const int* __restrict__ part, int* __restrict__ partscan,
                            int nb) {
    __shared__ int sd[128];
    int t = threadIdx.x;
    int s = (t < nb) ? part[t] : 0;
    sd[t] = s;
#pragma unroll
    for (int off = 1; off < 128; off <<= 1) {
        __syncthreads();
        int v = (t >= off) ? sd[t - off] : 0;
        __syncthreads();
        sd[t] += v;
    }
    __syncthreads();
    if (t < nb) partscan[t] = sd[t] - s;
}

__global__ void k_scan_add(const int* __restrict__ scan, const int* __restrict__ partscan,
                           int* __restrict__ start, int* __restrict__ cursor,
                           int n, int E) {
    int i = blockIdx.x * blockDim.x + threadIdx.x;
    if (i < n) {
        int v = scan[i] + partscan[i >> 10];
        start[i] = v;
        cursor[i] = v;
    }
    if (i == 0) start[n] = E;
}

// ---------------- per-edge weight + direct CSR fill --------------------------
__global__ __launch_bounds__(256) void k_edge_w(const int* __restrict__ edges,
                                                const float* __restrict__ verts,
                                                const float* __restrict__ nacc,
                                                const float* __restrict__ W1,
                                                const float* __restrict__ b1,
                                                const float* __restrict__ W2,
                                                const float* __restrict__ b2,
                                                int* __restrict__ cursor,
                                                int* __restrict__ csr_src,
                                                float* __restrict__ csr_w, int E) {
    __shared__ float sW1[96];
    __shared__ float sb1[32];
    __shared__ float sW2[192];
    __shared__ float sb2[6];
    int tid = threadIdx.x;
    for (int i = tid; i < 96;  i += blockDim.x) sW1[i] = W1[i];
    for (int i = tid; i < 32;  i += blockDim.x) sb1[i] = b1[i];
    for (int i = tid; i < 192; i += blockDim.x) sW2[i] = W2[i];
    for (int i = tid; i < 6;   i += blockDim.x) sb2[i] = b2[i];
    __syncthreads();

    int e = blockIdx.x * blockDim.x + tid;
    if (e >= E) return;
    int src = __ldg(edges + e);
    int dst = __ldg(edges + E + e);

    float dx = __ldg(verts + 3 * dst)     - __ldg(verts + 3 * src);
    float dy = __ldg(verts + 3 * dst + 1) - __ldg(verts + 3 * src + 1);
    float dz = __ldg(verts + 3 * dst + 2) - __ldg(verts + 3 * src + 2);
    // inline normal normalization (same math as reference)
    float rx = __ldg(nacc + 3 * src), ry = __ldg(nacc + 3 * src + 1), rz = __ldg(nacc + 3 * src + 2);
    float len = sqrtf(rx * rx + ry * ry + rz * rz);
    float inv = 1.0f / (len + 1e-8f);
    float nx = rx * inv, ny = ry * inv, nz = rz * inv;

    float dot = dx * nx + dy * ny + dz * nz;
    float t0 = dx - dot * nx, t1 = dy - dot * ny, t2 = dz - dot * nz;

    float th[6];
#pragma unroll
    for (int m = 0; m < 6; m++) th[m] = sb2[m];
#pragma unroll
    for (int j = 0; j < 32; j++) {
        float h = sb1[j] + t0 * sW1[j] + t1 * sW1[32 + j] + t2 * sW1[64 + j];
        h = fmaxf(h, 0.0f);
#pragma unroll
        for (int m = 0; m < 6; m++) th[m] += h * sW2[j * 6 + m];
    }
    float s0 = th[0] * t0 + th[1] * t1 + th[2] * t2;
    float s1 = th[1] * t0 + th[3] * t1 + th[4] * t2;
    float s2 = th[2] * t0 + th[4] * t1 + th[5] * t2;
    float q = s0 * s0 + s1 * s1 + s2 * s2;
    float wv = expf(-q);

    int pos = atomicAdd(&cursor[dst], 1);
    csr_src[pos] = src;
    csr_w[pos] = wv;
}

// ---------------- gather aggregation: warp per dst vertex, 4-wide MLP --------
__global__ __launch_bounds__(256) void k_gather(const int* __restrict__ start,
                                                const int* __restrict__ csr_src,
                                                const float* __restrict__ csr_w,
                                                const float* __restrict__ x,
                                                float* __restrict__ p, int n) {
    int v = (blockIdx.x * blockDim.x + threadIdx.x) >> 5;
    int lane = threadIdx.x & 31;
    if (v >= n) return;
    int beg = __ldg(start + v);
    int end = __ldg(start + v + 1);
    float4 acc = make_float4(0.f, 0.f, 0.f, 0.f);
    float dsum = 0.0f;
    int i = beg;
    for (; i + 4 <= end; i += 4) {
        int s0 = __ldg(csr_src + i + 0);
        int s1 = __ldg(csr_src + i + 1);
        int s2 = __ldg(csr_src + i + 2);
        int s3 = __ldg(csr_src + i + 3);
        float w0 = __ldg(csr_w + i + 0);
        float w1 = __ldg(csr_w + i + 1);
        float w2 = __ldg(csr_w + i + 2);
        float w3 = __ldg(csr_w + i + 3);
        float4 a = __ldg((const float4*)(x + (size_t)s0 * C) + lane);
        float4 b = __ldg((const float4*)(x + (size_t)s1 * C) + lane);
        float4 c = __ldg((const float4*)(x + (size_t)s2 * C) + lane);
        float4 d = __ldg((const float4*)(x + (size_t)s3 * C) + lane);
        dsum += (w0 + w1) + (w2 + w3);
        acc.x += w0 * a.x + w1 * b.x + w2 * c.x + w3 * d.x;
        acc.y += w0 * a.y + w1 * b.y + w2 * c.y + w3 * d.y;
        acc.z += w0 * a.z + w1 * b.z + w2 * c.z + w3 * d.z;
        acc.w += w0 * a.w + w1 * b.w + w2 * c.w + w3 * d.w;
    }
    for (; i < end; i++) {
        int s = __ldg(csr_src + i);
        float we = __ldg(csr_w + i);
        float4 xv = __ldg((const float4*)(x + (size_t)s * C) + lane);
        dsum += we;
        acc.x += we * xv.x; acc.y += we * xv.y; acc.z += we * xv.z; acc.w += we * xv.w;
    }
    float rd = 1.0f / (dsum + 1e-5f);
    acc.x *= rd; acc.y *= rd; acc.z *= rd; acc.w *= rd;
    *((float4*)(p + (size_t)v * C) + lane) = acc;
}

// ---------------- per-column stats -------------------------------------------
__global__ void k_stats(const float* __restrict__ p, float* __restrict__ stats, int n) {
    int c = threadIdx.x;  // 128 threads
    float s1 = 0.0f, s2 = 0.0f;
    for (int r = blockIdx.x; r < n; r += gridDim.x) {
        float v = __ldg(p + (size_t)r * C + c);
        s1 += v;
        s2 += v * v;
    }
    atomicAdd(&stats[c], s1);
    atomicAdd(&stats[C + c], s2);
}

__global__ void k_finalize(const float* __restrict__ stats, float* __restrict__ mu,
                           float* __restrict__ rstd, int n) {
    int c = threadIdx.x;
    float m = stats[c] / (float)n;
    float var = (stats[C + c] - (float)n * m * m) / (float)(n - 1);
    var = fmaxf(var, 0.0f);
    mu[c] = m;
    rstd[c] = 1.0f / (sqrtf(var) + 1e-5f);
}

// ---------------- final: normalize + ELU -------------------------------------
__global__ void k_final(const float* __restrict__ p, const float* __restrict__ mu,
                        const float* __restrict__ rstd, float* __restrict__ out, int n) {
    size_t idx = (size_t)blockIdx.x * blockDim.x + threadIdx.x;
    if (idx >= (size_t)n * C) return;
    int c = (int)(idx & 127);
    float y = (p[idx] - __ldg(mu + c)) * __ldg(rstd + c);
    out[idx] = (y > 0.0f) ? y : expm1f(y);
}

// ---------------- launch -----------------------------------------------------
extern "C" void kernel_launch(void* const* d_in, const int* in_sizes, int n_in,
                              void* d_out, int out_size) {
    const float* features = (const float*)d_in[0];
    const float* vertices = (const float*)d_in[1];
    const int*   edges    = (const int*)d_in[2];
    const int*   faces    = (const int*)d_in[3];
    const float* W1       = (const float*)d_in[4];
    const float* b1       = (const float*)d_in[5];
    const float* W2       = (const float*)d_in[6];
    const float* b2       = (const float*)d_in[7];
    const float* Wlin     = (const float*)d_in[8];
    const float* blin     = (const float*)d_in[9];

    int n = in_sizes[0] / C;
    int e = in_sizes[2] / 2;
    int f = in_sizes[3] / 3;
    if (n > NMAX) n = NMAX;
    if (e > EMAX) e = EMAX;
    if (f > FMAX) f = FMAX;

    float *p_x, *p_p, *p_nacc, *p_stats, *p_mu, *p_rstd, *p_csrw;
    int *p_deg, *p_scan, *p_part, *p_partscan, *p_start, *p_cursor, *p_csrsrc;
    uint32_t *p_bh, *p_bl;
    cudaGetSymbolAddress((void**)&p_x, g_x);
    cudaGetSymbolAddress((void**)&p_p, g_p);
    cudaGetSymbolAddress((void**)&p_nacc, g_nacc);
    cudaGetSymbolAddress((void**)&p_stats, g_stats);
    cudaGetSymbolAddress((void**)&p_mu, g_mu);
    cudaGetSymbolAddress((void**)&p_rstd, g_rstd);
    cudaGetSymbolAddress((void**)&p_deg, g_deg);
    cudaGetSymbolAddress((void**)&p_scan, g_scan);
    cudaGetSymbolAddress((void**)&p_part, g_part);
    cudaGetSymbolAddress((void**)&p_partscan, g_partscan);
    cudaGetSymbolAddress((void**)&p_start, g_start);
    cudaGetSymbolAddress((void**)&p_cursor, g_cursor);
    cudaGetSymbolAddress((void**)&p_csrsrc, g_csr_src);
    cudaGetSymbolAddress((void**)&p_csrw, g_csr_w);
    cudaGetSymbolAddress((void**)&p_bh, g_Bh);
    cudaGetSymbolAddress((void**)&p_bl, g_Bl);

    float* out = (float*)d_out;

    const int GEMM_SMEM = 2 * 128 * BPITCH * 4;   // 69632 bytes
    cudaFuncSetAttribute(k_gemm_mma, cudaFuncAttributeMaxDynamicSharedMemorySize, GEMM_SMEM);

    int nb = (n + 1023) / 1024;                   // scan blocks (<=128)

    k_zero_misc<<<(n * 3 + 255) / 256, 256>>>(p_nacc, p_deg, p_stats, n);
    k_count<<<(e + 255) / 256, 256>>>(edges, p_deg, e);
    k_face<<<(f + 255) / 256, 256>>>(faces, vertices, p_nacc, f);
    k_prepB<<<32, 256>>>(Wlin, p_bh, p_bl);
    k_gemm_mma<<<(n + 127) / 128, 256, GEMM_SMEM>>>(features, p_bh, p_bl,
                                                    blin, p_x, n);
    k_scan_block<<<nb, 256>>>(p_deg, p_scan, p_part, n);
    k_scan_part<<<1, 128>>>(p_part, p_partscan, nb);
    k_scan_add<<<(n + 255) / 256, 256>>>(p_scan, p_partscan, p_start, p_cursor, n, e);
    k_edge_w<<<(e + 255) / 256, 256>>>(edges, vertices, p_nacc, W1, b1, W2, b2,
                                       p_cursor, p_csrsrc, p_csrw, e);
    k_gather<<<(n * 32 + 255) / 256, 256>>>(p_start, p_csrsrc, p_csrw, p_x, p_p, n);
    k_stats<<<512, 128>>>(p_p, p_stats, n);
    k_finalize<<<1, C>>>(p_stats, p_mu, p_rstd, n);
    k_final<<<((size_t)n * C + 255) / 256, 256>>>(p_p, p_mu, p_rstd, out, n);
}

// round 10
// speedup vs baseline: 1.8104x; 1.0656x over previous
#include <cuda_runtime.h>
#include <cuda_bf16.h>
#include <cstdint>
#include <cstddef>

#define NMAX 100000
#define EMAX 600000
#define FMAX 200000
#define C    128

// ---------------- scratch (static device globals; no runtime alloc) ----------
__device__ float g_x[(size_t)NMAX * C];      // features @ Wlin + blin
__device__ float g_p[(size_t)NMAX * C];      // aggregated & den-normalized rows
__device__ float g_nacc[NMAX * 3];           // accumulated face normals (raw)
__device__ float g_stats[256];               // colsum[128], colsum2[128]
// CSR-by-dst
__device__ int   g_deg[NMAX];
__device__ int   g_scan[NMAX];               // in-block exclusive scan
__device__ int   g_part[128];                // block partial sums
__device__ int   g_partscan[128];
__device__ int   g_start[NMAX + 1];
__device__ int   g_cursor[NMAX];
__device__ int   g_csr_src[EMAX];
__device__ float g_csr_w[EMAX];
// pre-converted W as bf16 hi/lo pairs, layout [n][k-pair] with pitch 68 u32
#define BPITCH 68
__device__ uint32_t g_Bh[128 * BPITCH];
__device__ uint32_t g_Bl[128 * BPITCH];

// ---------------- W pre-convert: fp32 -> bf16 hi/lo [n][k] pitch-68 ----------
__global__ void k_prepB(const float* __restrict__ W, uint32_t* __restrict__ bh,
                        uint32_t* __restrict__ bl) {
    int idx = blockIdx.x * blockDim.x + threadIdx.x;   // 128 cols * 64 k-pairs
    if (idx >= 128 * 64) return;
    int c = idx >> 6, kp = idx & 63;
    float v0 = __ldg(W + (size_t)(2 * kp) * C + c);
    float v1 = __ldg(W + (size_t)(2 * kp + 1) * C + c);
    __nv_bfloat16 h0 = __float2bfloat16_rn(v0);
    __nv_bfloat16 h1 = __float2bfloat16_rn(v1);
    __nv_bfloat16 l0 = __float2bfloat16_rn(v0 - __bfloat162float(h0));
    __nv_bfloat16 l1 = __float2bfloat16_rn(v1 - __bfloat162float(h1));
    __nv_bfloat162 H(h0, h1), L(l0, l1);
    bh[c * BPITCH + kp] = *(uint32_t*)&H;
    bl[c * BPITCH + kp] = *(uint32_t*)&L;
}

// ---------------- zero helper ------------------------------------------------
__global__ void k_zero_misc(float* __restrict__ nacc, int* __restrict__ deg,
                            float* __restrict__ stats, int n) {
    int i = blockIdx.x * blockDim.x + threadIdx.x;
    if (i < n * 3) nacc[i] = 0.0f;
    if (i < n) deg[i] = 0;
    if (i < 256) stats[i] = 0.0f;
}

// ---------------- face normals (scatter) + dst degree count ------------------
__global__ void k_face_count(const int* __restrict__ faces, const float* __restrict__ verts,
                             const int* __restrict__ edges, float* __restrict__ nacc,
                             int* __restrict__ deg, int F, int E) {
    int t = blockIdx.x * blockDim.x + threadIdx.x;
    if (t < F) {
        int f = t;
        int i0 = __ldg(faces + f);
        int i1 = __ldg(faces + F + f);
        int i2 = __ldg(faces + 2 * F + f);
        float v0x = __ldg(verts + 3 * i0), v0y = __ldg(verts + 3 * i0 + 1), v0z = __ldg(verts + 3 * i0 + 2);
        float v1x = __ldg(verts + 3 * i1), v1y = __ldg(verts + 3 * i1 + 1), v1z = __ldg(verts + 3 * i1 + 2);
        float v2x = __ldg(verts + 3 * i2), v2y = __ldg(verts + 3 * i2 + 1), v2z = __ldg(verts + 3 * i2 + 2);
        float ax = v1x - v0x, ay = v1y - v0y, az = v1z - v0z;
        float bx = v2x - v0x, by = v2y - v0y, bz = v2z - v0z;
        float nx = ay * bz - az * by;
        float ny = az * bx - ax * bz;
        float nz = ax * by - ay * bx;
        atomicAdd(&nacc[3 * i0 + 0], nx); atomicAdd(&nacc[3 * i0 + 1], ny); atomicAdd(&nacc[3 * i0 + 2], nz);
        atomicAdd(&nacc[3 * i1 + 0], nx); atomicAdd(&nacc[3 * i1 + 1], ny); atomicAdd(&nacc[3 * i1 + 2], nz);
        atomicAdd(&nacc[3 * i2 + 0], nx); atomicAdd(&nacc[3 * i2 + 1], ny); atomicAdd(&nacc[3 * i2 + 2], nz);
    } else {
        int e = t - F;
        if (e < E) atomicAdd(&deg[__ldg(edges + E + e)], 1);
    }
}

// ---------------- mma.sync helpers -------------------------------------------
__device__ __forceinline__ void mma16816(float* c, const uint32_t* a,
                                         uint32_t b0, uint32_t b1) {
    asm volatile(
        "mma.sync.aligned.m16n8k16.row.col.f32.bf16.bf16.f32 "
        "{%0,%1,%2,%3}, {%4,%5,%6,%7}, {%8,%9}, {%0,%1,%2,%3};"
        : "+f"(c[0]), "+f"(c[1]), "+f"(c[2]), "+f"(c[3])
        : "r"(a[0]), "r"(a[1]), "r"(a[2]), "r"(a[3]), "r"(b0), "r"(b1));
}

__device__ __forceinline__ void cvt2(float2 v, uint32_t& hi, uint32_t& lo) {
    __nv_bfloat16 h0 = __float2bfloat16_rn(v.x);
    __nv_bfloat16 h1 = __float2bfloat16_rn(v.y);
    __nv_bfloat16 l0 = __float2bfloat16_rn(v.x - __bfloat162float(h0));
    __nv_bfloat16 l1 = __float2bfloat16_rn(v.y - __bfloat162float(h1));
    __nv_bfloat162 H(h0, h1), L(l0, l1);
    hi = *(uint32_t*)&H;
    lo = *(uint32_t*)&L;
}

// ---------------- bf16x3 mma GEMM: x = feat @ W + b --------------------------
extern __shared__ uint32_t sB[];   // [2][128*BPITCH] hi then lo

__global__ __launch_bounds__(256) void k_gemm_mma(const float* __restrict__ feat,
                                                  const uint32_t* __restrict__ gBh,
                                                  const uint32_t* __restrict__ gBl,
                                                  const float* __restrict__ bias,
                                                  float* __restrict__ xout, int n) {
    const int BSZ = 128 * BPITCH;          // 8704 u32
    int tid = threadIdx.x;
    {
        const float4* s1 = (const float4*)gBh;
        const float4* s2 = (const float4*)gBl;
        float4* d1 = (float4*)sB;
        float4* d2 = (float4*)(sB + BSZ);
        for (int i = tid; i < BSZ / 4; i += 256) { d1[i] = __ldg(s1 + i); d2[i] = __ldg(s2 + i); }
    }
    __syncthreads();

    int warp = tid >> 5, lane = tid & 31;
    int gid = lane >> 2, tg = lane & 3;
    int r0 = blockIdx.x * 128 + warp * 16 + gid;
    int r1 = r0 + 8;
    int r0c = (r0 < n) ? r0 : (n - 1);
    int r1c = (r1 < n) ? r1 : (n - 1);
    const float* A0 = feat + (size_t)r0c * C;
    const float* A1 = feat + (size_t)r1c * C;

    float acc[16][4];
#pragma unroll
    for (int t = 0; t < 16; t++) { acc[t][0] = acc[t][1] = acc[t][2] = acc[t][3] = 0.0f; }

    const uint32_t* Bh = sB;
    const uint32_t* Bl = sB + BSZ;

#pragma unroll
    for (int ch = 0; ch < 8; ch++) {
        int k0 = ch * 16 + tg * 2;
        float2 p00 = __ldg((const float2*)(A0 + k0));
        float2 p10 = __ldg((const float2*)(A1 + k0));
        float2 p01 = __ldg((const float2*)(A0 + k0 + 8));
        float2 p11 = __ldg((const float2*)(A1 + k0 + 8));
        uint32_t ah[4], al[4];
        cvt2(p00, ah[0], al[0]);
        cvt2(p10, ah[1], al[1]);
        cvt2(p01, ah[2], al[2]);
        cvt2(p11, ah[3], al[3]);
        int bbase = ch * 8 + tg;
#pragma unroll
        for (int t = 0; t < 16; t++) {
            int ci = (t * 8 + gid) * BPITCH + bbase;
            uint32_t bh0 = Bh[ci], bh1 = Bh[ci + 4];
            uint32_t bl0 = Bl[ci], bl1 = Bl[ci + 4];
            mma16816(acc[t], ah, bh0, bh1);
            mma16816(acc[t], ah, bl0, bl1);
            mma16816(acc[t], al, bh0, bh1);
        }
    }

#pragma unroll
    for (int t = 0; t < 16; t++) {
        int c0 = t * 8 + tg * 2;
        float2 bv = __ldg((const float2*)(bias + c0));
        if (r0 < n) {
            float2 o = make_float2(acc[t][0] + bv.x, acc[t][1] + bv.y);
            *(float2*)(xout + (size_t)r0 * C + c0) = o;
        }
        if (r1 < n) {
            float2 o = make_float2(acc[t][2] + bv.x, acc[t][3] + bv.y);
            *(float2*)(xout + (size_t)r1 * C + c0) = o;
        }
    }
}

// ---------------- two-level exclusive scan over deg --------------------------
__global__ __launch_bounds__(256) void k_scan_block(const int* __restrict__ deg,
                                                    int* __restrict__ scan,
                                                    int* __restrict__ part, int n) {
    __shared__ int sd[256];
    int t = threadIdx.x;
    int base = blockIdx.x * 1024 + t * 4;
    int d0 = (base + 0 < n) ? deg[base + 0] : 0;
    int d1 = (base + 1 < n) ? deg[base + 1] : 0;
    int d2 = (base + 2 < n) ? deg[base + 2] : 0;
    int d3 = (base + 3 < n) ? deg[base + 3] : 0;
    int s = d0 + d1 + d2 + d3;
    sd[t] = s;
#pragma unroll
    for (int off = 1; off < 256; off <<= 1) {
        __syncthreads();
        int v = (t >= off) ? sd[t - off] : 0;
        __syncthreads();
        sd[t] += v;
    }
    __syncthreads();
    int excl = sd[t] - s;
    if (base + 0 < n) scan[base + 0] = excl;
    if (base + 1 < n) scan[base + 1] = excl + d0;
    if (base + 2 < n) scan[base + 2] = excl + d0 + d1;
    if (base + 3 < n) scan[base + 3] = excl + d0 + d1 + d2;
    if (t == 255) part[blockIdx.x] = sd[255];
}

__global__ void k_scan_part(const int* __restrict__ part, int* __restrict__ partscan,
                            int nb) {
    __shared__ int sd[128];
    int t = threadIdx.x;
    int s = (t < nb) ? part[t] : 0;
    sd[t] = s;
#pragma unroll
    for (int off = 1; off < 128; off <<= 1) {
        __syncthreads();
        int v = (t >= off) ? sd[t - off] : 0;
        __syncthreads();
        sd[t] += v;
    }
    __syncthreads();
    if (t < nb) partscan[t] = sd[t] - s;
}

__global__ void k_scan_add(const int* __restrict__ scan, const int* __restrict__ partscan,
                           int* __restrict__ start, int* __restrict__ cursor,
                           int n, int E) {
    int i = blockIdx.x * blockDim.x + threadIdx.x;
    if (i < n) {
        int v = scan[i] + partscan[i >> 10];
        start[i] = v;
        cursor[i] = v;
    }
    if (i == 0) start[n] = E;
}

// ---------------- per-edge weight + direct CSR fill --------------------------
__global__ __launch_bounds__(256) void k_edge_w(const int* __restrict__ edges,
                                                const float* __restrict__ verts,
                                                const float* __restrict__ nacc,
                                                const float* __restrict__ W1,
                                                const float* __restrict__ b1,
                                                const float* __restrict__ W2,
                                                const float* __restrict__ b2,
                                                int* __restrict__ cursor,
                                                int* __restrict__ csr_src,
                                                float* __restrict__ csr_w, int E) {
    __shared__ float sW1[96];
    __shared__ float sb1[32];
    __shared__ float sW2[192];
    __shared__ float sb2[6];
    int tid = threadIdx.x;
    for (int i = tid; i < 96;  i += blockDim.x) sW1[i] = W1[i];
    for (int i = tid; i < 32;  i += blockDim.x) sb1[i] = b1[i];
    for (int i = tid; i < 192; i += blockDim.x) sW2[i] = W2[i];
    for (int i = tid; i < 6;   i += blockDim.x) sb2[i] = b2[i];
    __syncthreads();

    int e = blockIdx.x * blockDim.x + tid;
    if (e >= E) return;
    int src = __ldg(edges + e);
    int dst = __ldg(edges + E + e);

    float dx = __ldg(verts + 3 * dst)     - __ldg(verts + 3 * src);
    float dy = __ldg(verts + 3 * dst + 1) - __ldg(verts + 3 * src + 1);
    float dz = __ldg(verts + 3 * dst + 2) - __ldg(verts + 3 * src + 2);
    float rx = __ldg(nacc + 3 * src), ry = __ldg(nacc + 3 * src + 1), rz = __ldg(nacc + 3 * src + 2);
    float len = sqrtf(rx * rx + ry * ry + rz * rz);
    float inv = 1.0f / (len + 1e-8f);
    float nx = rx * inv, ny = ry * inv, nz = rz * inv;

    float dot = dx * nx + dy * ny + dz * nz;
    float t0 = dx - dot * nx, t1 = dy - dot * ny, t2 = dz - dot * nz;

    float th[6];
#pragma unroll
    for (int m = 0; m < 6; m++) th[m] = sb2[m];
#pragma unroll
    for (int j = 0; j < 32; j++) {
        float h = sb1[j] + t0 * sW1[j] + t1 * sW1[32 + j] + t2 * sW1[64 + j];
        h = fmaxf(h, 0.0f);
#pragma unroll
        for (int m = 0; m < 6; m++) th[m] += h * sW2[j * 6 + m];
    }
    float s0 = th[0] * t0 + th[1] * t1 + th[2] * t2;
    float s1 = th[1] * t0 + th[3] * t1 + th[4] * t2;
    float s2 = th[2] * t0 + th[4] * t1 + th[5] * t2;
    float q = s0 * s0 + s1 * s1 + s2 * s2;
    float wv = expf(-q);

    int pos = atomicAdd(&cursor[dst], 1);
    csr_src[pos] = src;
    csr_w[pos] = wv;
}

// ---------------- gather aggregation: warp per dst vertex, 4-wide MLP --------
__global__ __launch_bounds__(256) void k_gather(const int* __restrict__ start,
                                                const int* __restrict__ csr_src,
                                                const float* __restrict__ csr_w,
                                                const float* __restrict__ x,
                                                float* __restrict__ p, int n) {
    int v = (blockIdx.x * blockDim.x + threadIdx.x) >> 5;
    int lane = threadIdx.x & 31;
    if (v >= n) return;
    int beg = __ldg(start + v);
    int end = __ldg(start + v + 1);
    float4 acc = make_float4(0.f, 0.f, 0.f, 0.f);
    float dsum = 0.0f;
    int i = beg;
    for (; i + 4 <= end; i += 4) {
        int s0 = __ldg(csr_src + i + 0);
        int s1 = __ldg(csr_src + i + 1);
        int s2 = __ldg(csr_src + i + 2);
        int s3 = __ldg(csr_src + i + 3);
        float w0 = __ldg(csr_w + i + 0);
        float w1 = __ldg(csr_w + i + 1);
        float w2 = __ldg(csr_w + i + 2);
        float w3 = __ldg(csr_w + i + 3);
        float4 a = __ldg((const float4*)(x + (size_t)s0 * C) + lane);
        float4 b = __ldg((const float4*)(x + (size_t)s1 * C) + lane);
        float4 c = __ldg((const float4*)(x + (size_t)s2 * C) + lane);
        float4 d = __ldg((const float4*)(x + (size_t)s3 * C) + lane);
        dsum += (w0 + w1) + (w2 + w3);
        acc.x += w0 * a.x + w1 * b.x + w2 * c.x + w3 * d.x;
        acc.y += w0 * a.y + w1 * b.y + w2 * c.y + w3 * d.y;
        acc.z += w0 * a.z + w1 * b.z + w2 * c.z + w3 * d.z;
        acc.w += w0 * a.w + w1 * b.w + w2 * c.w + w3 * d.w;
    }
    for (; i < end; i++) {
        int s = __ldg(csr_src + i);
        float we = __ldg(csr_w + i);
        float4 xv = __ldg((const float4*)(x + (size_t)s * C) + lane);
        dsum += we;
        acc.x += we * xv.x; acc.y += we * xv.y; acc.z += we * xv.z; acc.w += we * xv.w;
    }
    float rd = 1.0f / (dsum + 1e-5f);
    acc.x *= rd; acc.y *= rd; acc.z *= rd; acc.w *= rd;
    *((float4*)(p + (size_t)v * C) + lane) = acc;
}

// ---------------- per-column stats -------------------------------------------
__global__ void k_stats(const float* __restrict__ p, float* __restrict__ stats, int n) {
    int c = threadIdx.x;  // 128 threads
    float s1 = 0.0f, s2 = 0.0f;
    for (int r = blockIdx.x; r < n; r += gridDim.x) {
        float v = __ldg(p + (size_t)r * C + c);
        s1 += v;
        s2 += v * v;
    }
    atomicAdd(&stats[c], s1);
    atomicAdd(&stats[C + c], s2);
}

// ---------------- final: (inline mu/rstd) normalize + ELU, float4 ------------
__global__ __launch_bounds__(256) void k_final(const float* __restrict__ p,
                                               const float* __restrict__ stats,
                                               float* __restrict__ out, int n) {
    __shared__ float smu[C];
    __shared__ float srstd[C];
    int tid = threadIdx.x;
    if (tid < C) {
        float m = stats[tid] / (float)n;
        float var = (stats[C + tid] - (float)n * m * m) / (float)(n - 1);
        var = fmaxf(var, 0.0f);
        smu[tid] = m;
        srstd[tid] = 1.0f / (sqrtf(var) + 1e-5f);
    }
    __syncthreads();
    size_t i4 = (size_t)blockIdx.x * blockDim.x + tid;    // float4 index
    if (i4 >= (size_t)n * 32) return;
    int c4 = (int)(i4 & 31) * 4;
    float4 v = __ldg((const float4*)p + i4);
    float y0 = (v.x - smu[c4 + 0]) * srstd[c4 + 0];
    float y1 = (v.y - smu[c4 + 1]) * srstd[c4 + 1];
    float y2 = (v.z - smu[c4 + 2]) * srstd[c4 + 2];
    float y3 = (v.w - smu[c4 + 3]) * srstd[c4 + 3];
    float4 o;
    o.x = (y0 > 0.0f) ? y0 : expm1f(y0);
    o.y = (y1 > 0.0f) ? y1 : expm1f(y1);
    o.z = (y2 > 0.0f) ? y2 : expm1f(y2);
    o.w = (y3 > 0.0f) ? y3 : expm1f(y3);
    ((float4*)out)[i4] = o;
}

// ---------------- launch -----------------------------------------------------
extern "C" void kernel_launch(void* const* d_in, const int* in_sizes, int n_in,
                              void* d_out, int out_size) {
    const float* features = (const float*)d_in[0];
    const float* vertices = (const float*)d_in[1];
    const int*   edges    = (const int*)d_in[2];
    const int*   faces    = (const int*)d_in[3];
    const float* W1       = (const float*)d_in[4];
    const float* b1       = (const float*)d_in[5];
    const float* W2       = (const float*)d_in[6];
    const float* b2       = (const float*)d_in[7];
    const float* Wlin     = (const float*)d_in[8];
    const float* blin     = (const float*)d_in[9];

    int n = in_sizes[0] / C;
    int e = in_sizes[2] / 2;
    int f = in_sizes[3] / 3;
    if (n > NMAX) n = NMAX;
    if (e > EMAX) e = EMAX;
    if (f > FMAX) f = FMAX;

    float *p_x, *p_p, *p_nacc, *p_stats, *p_csrw;
    int *p_deg, *p_scan, *p_part, *p_partscan, *p_start, *p_cursor, *p_csrsrc;
    uint32_t *p_bh, *p_bl;
    cudaGetSymbolAddress((void**)&p_x, g_x);
    cudaGetSymbolAddress((void**)&p_p, g_p);
    cudaGetSymbolAddress((void**)&p_nacc, g_nacc);
    cudaGetSymbolAddress((void**)&p_stats, g_stats);
    cudaGetSymbolAddress((void**)&p_deg, g_deg);
    cudaGetSymbolAddress((void**)&p_scan, g_scan);
    cudaGetSymbolAddress((void**)&p_part, g_part);
    cudaGetSymbolAddress((void**)&p_partscan, g_partscan);
    cudaGetSymbolAddress((void**)&p_start, g_start);
    cudaGetSymbolAddress((void**)&p_cursor, g_cursor);
    cudaGetSymbolAddress((void**)&p_csrsrc, g_csr_src);
    cudaGetSymbolAddress((void**)&p_csrw, g_csr_w);
    cudaGetSymbolAddress((void**)&p_bh, g_Bh);
    cudaGetSymbolAddress((void**)&p_bl, g_Bl);

    float* out = (float*)d_out;

    const int GEMM_SMEM = 2 * 128 * BPITCH * 4;   // 69632 bytes
    cudaFuncSetAttribute(k_gemm_mma, cudaFuncAttributeMaxDynamicSharedMemorySize, GEMM_SMEM);

    int nb = (n + 1023) / 1024;                   // scan blocks (<=128)

    k_prepB<<<32, 256>>>(Wlin, p_bh, p_bl);                                        // 0
    k_zero_misc<<<(n * 3 + 255) / 256, 256>>>(p_nacc, p_deg, p_stats, n);          // 1
    k_face_count<<<(f + e + 255) / 256, 256>>>(faces, vertices, edges, p_nacc,
                                               p_deg, f, e);                       // 2
    k_gemm_mma<<<(n + 127) / 128, 256, GEMM_SMEM>>>(features, p_bh, p_bl,
                                                    blin, p_x, n);                 // 3 (ncu)
    k_scan_block<<<nb, 256>>>(p_deg, p_scan, p_part, n);                           // 4
    k_scan_part<<<1, 128>>>(p_part, p_partscan, nb);                               // 5
    k_scan_add<<<(n + 255) / 256, 256>>>(p_scan, p_partscan, p_start, p_cursor, n, e); // 6
    k_edge_w<<<(e + 255) / 256, 256>>>(edges, vertices, p_nacc, W1, b1, W2, b2,
                                       p_cursor, p_csrsrc, p_csrw, e);             // 7
    k_gather<<<(n * 32 + 255) / 256, 256>>>(p_start, p_csrsrc, p_csrw, p_x, p_p, n); // 8
    k_stats<<<512, 128>>>(p_p, p_stats, n);                                        // 9
    k_final<<<(n * 32 + 255) / 256, 256>>>(p_p, p_stats, out, n);                  // 10
}